// round 14
// baseline (speedup 1.0000x reference)
#include <cuda_runtime.h>
#include <cuda_fp16.h>
#include <utility>
#include <cstddef>

using u64 = unsigned long long;

// ---------------------------------------------------------------------------
// packed f32x2 primitives (FFMA2 exists only via PTX fma.rn.f32x2)
// ---------------------------------------------------------------------------
__device__ __forceinline__ u64 pack2(float lo, float hi) {
    u64 r; asm("mov.b64 %0, {%1, %2};" : "=l"(r) : "f"(lo), "f"(hi)); return r;
}
__device__ __forceinline__ void unpack2(u64 v, float& lo, float& hi) {
    asm("mov.b64 {%0, %1}, %2;" : "=f"(lo), "=f"(hi) : "l"(v));
}
__device__ __forceinline__ void fma2(u64& d, u64 a, u64 b) {
    asm("fma.rn.f32x2 %0, %1, %2, %3;" : "=l"(d) : "l"(a), "l"(b), "l"(d));
}
__device__ __forceinline__ float hlo(unsigned v) {
    __half2 h = *reinterpret_cast<__half2*>(&v); return __low2float(h);
}
__device__ __forceinline__ float hhi(unsigned v) {
    __half2 h = *reinterpret_cast<__half2*>(&v); return __high2float(h);
}

// 8 packed FMAs covering 16 permuted blade positions.
// Position order: blades [1,2, 3,4, 5,6, 7,8, 9,10, 11,12, 13,14, 0,15]
// pair grades:     g1    g1   g2   g2   g2    g3     g3    (g0,g4)
#define DO8(acc, qa, qb, qc, qd, p0, p1, p2, p3)                         \
    do {                                                                 \
        fma2((acc)[0], (qa).x, (p0)); fma2((acc)[1], (qa).y, (p0));      \
        fma2((acc)[2], (qb).x, (p1)); fma2((acc)[3], (qb).y, (p1));      \
        fma2((acc)[4], (qc).x, (p1)); fma2((acc)[5], (qc).y, (p2));      \
        fma2((acc)[6], (qd).x, (p2)); fma2((acc)[7], (qd).y, (p3));      \
    } while (0)

// unpack 8 pairs (permuted positions) into blade-indexed scalars
#define UNPK(acc, arr)                                                   \
    do {                                                                 \
        unpack2((acc)[0], (arr)[1],  (arr)[2]);                          \
        unpack2((acc)[1], (arr)[3],  (arr)[4]);                          \
        unpack2((acc)[2], (arr)[5],  (arr)[6]);                          \
        unpack2((acc)[3], (arr)[7],  (arr)[8]);                          \
        unpack2((acc)[4], (arr)[9],  (arr)[10]);                         \
        unpack2((acc)[5], (arr)[11], (arr)[12]);                         \
        unpack2((acc)[6], (arr)[13], (arr)[14]);                         \
        unpack2((acc)[7], (arr)[0],  (arr)[15]);                         \
    } while (0)

// build the 4 u64 packs for one tensor from 5 grade weights (f0..f4 = g0..g4)
#define MK_PACKS(p0, p1, p2, p3, f0, f1, f2, f3, f4)                      \
    u64 p0 = pack2(f1, f1), p1 = pack2(f2, f2),                           \
        p2 = pack2(f3, f3), p3 = pack2(f0, f4)

// ---------------------------------------------------------------------------
// Compile-time Clifford algebra G(3,0,1) tables
// Blade order: 1,e0,e1,e2,e3,e01,e02,e03,e12,e13,e23,e012,e013,e023,e123,e0123
// ---------------------------------------------------------------------------
namespace ga {

constexpr int MASK[16]  = {0,1,2,4,8,3,5,9,6,10,12,7,11,13,14,15};

constexpr int mask_to_idx(int m) {
    int r = 0;
    for (int i = 0; i < 16; i++) if (MASK[i] == m) r = i;
    return r;
}
constexpr int swaps(int a, int b) {
    int s = 0;
    for (int q = 0; q < 4; q++)
        if ((b >> q) & 1)
            for (int p = q + 1; p < 4; p++)
                if ((a >> p) & 1) s++;
    return s;
}
constexpr float rsign(int a, int b) { return (swaps(a, b) & 1) ? -1.0f : 1.0f; }

struct Tab { float s[16][16]; int k[16][16]; };

constexpr Tab make_gp() {
    Tab t{};
    for (int i = 0; i < 16; i++)
        for (int j = 0; j < 16; j++) {
            int a = MASK[i], b = MASK[j];
            float sg = rsign(a, b);
            if (a & b & 1) sg = 0.0f;            // e0^2 = 0
            t.s[i][j] = sg;
            t.k[i][j] = mask_to_idx(a ^ b);
        }
    return t;
}
constexpr float dsign(int i) { return rsign(MASK[i], 15 ^ MASK[i]); }
constexpr Tab make_join() {
    Tab t{};
    for (int i = 0; i < 16; i++)
        for (int j = 0; j < 16; j++) {
            int ci = 15 ^ MASK[i], cj = 15 ^ MASK[j];
            if (ci & cj) { t.s[i][j] = 0.0f; t.k[i][j] = 0; }
            else {
                int m = ci | cj;
                int p = mask_to_idx(15 ^ m);
                t.s[i][j] = dsign(i) * dsign(j) * rsign(ci, cj) * dsign(p);
                t.k[i][j] = p;
            }
        }
    return t;
}
constexpr Tab GP = make_gp();
constexpr Tab JN = make_join();

} // namespace ga

// static-for sparse bilinears (all indices compile-time)
template<int I, int J>
__device__ __forceinline__ void gp_term(float* p, const float* a, const float* b) {
    constexpr float s = ga::GP.s[I][J];
    constexpr int   k = ga::GP.k[I][J];
    if constexpr (s != 0.0f) p[k] += s * a[I] * b[J];
}
template<int I, int... Js>
__device__ __forceinline__ void gp_row(float* p, const float* a, const float* b,
                                       std::integer_sequence<int, Js...>) {
    (gp_term<I, Js>(p, a, b), ...);
}
template<int... Is>
__device__ __forceinline__ void gp_mat(float* p, const float* a, const float* b,
                                       std::integer_sequence<int, Is...>) {
    (gp_row<Is>(p, a, b, std::make_integer_sequence<int, 16>{}), ...);
}
template<int I, int J>
__device__ __forceinline__ void jn_term(float* p, const float* a, const float* b) {
    constexpr float s = ga::JN.s[I][J];
    constexpr int   k = ga::JN.k[I][J];
    if constexpr (s != 0.0f) p[k] += s * a[I] * b[J];
}
template<int I, int... Js>
__device__ __forceinline__ void jn_row(float* p, const float* a, const float* b,
                                       std::integer_sequence<int, Js...>) {
    (jn_term<I, Js>(p, a, b), ...);
}
template<int... Is>
__device__ __forceinline__ void jn_mat(float* p, const float* a, const float* b,
                                       std::integer_sequence<int, Is...>) {
    (jn_row<Is>(p, a, b, std::make_integer_sequence<int, 16>{}), ...);
}

// ---------------------------------------------------------------------------
// Problem constants: B=32, N=1024, Cin=64, Cout=64, H=32 -> 32768 tokens
// ---------------------------------------------------------------------------
static constexpr int TOKENS   = 32 * 1024;
static constexpr int NPAIRS   = TOKENS / 2;         // 16384 token pairs
static constexpr int WARPS_PB = 10;                 // 10 warps -> 204 reg budget
static constexpr int THREADS  = WARPS_PB * 32;      // 320
static constexpr int GRID     = 152;                // persistent, 1 CTA/SM

// fp16 weight tables (static __device__ -> no allocation)
// g_WPH: per (i, c) slot: 10 half2  [g0:(PX,PY) (JX,JY), g1:..., g2, g3, g4]
// g_WFH: per (cc, o) slot: 6 half2  [g0:(o,o+32), g1, g2, g3, g4, pad]
__device__ __align__(16) __half2 g_WPH[64 * 32 * 10];
__device__ __align__(16) __half2 g_WFH[64 * 32 * 6];

__global__ void prep_kernel(const float* __restrict__ wpx, const float* __restrict__ wpy,
                            const float* __restrict__ wjx, const float* __restrict__ wjy,
                            const float* __restrict__ wf) {
    int idx = blockIdx.x * blockDim.x + threadIdx.x;     // over 2048 (i,c) slots
    if (idx < 64 * 32) {
        int c = idx & 31;            // lane channel (c for proj, o for final)
        int i = idx >> 5;            // reduction index (i for proj, cc for final)
        #pragma unroll
        for (int g = 0; g < 5; g++) {
            int src = (g * 32 + c) * 64 + i;             // proj weights [5][32][64]
            g_WPH[idx * 10 + g * 2 + 0] = __floats2half2_rn(wpx[src], wpy[src]);
            g_WPH[idx * 10 + g * 2 + 1] = __floats2half2_rn(wjx[src], wjy[src]);
            // final weights [5][64 o][64 cc]; here c = o, i = cc
            g_WFH[idx * 6 + g] = __floats2half2_rn(wf[(g * 64 + c) * 64 + i],
                                                   wf[(g * 64 + c + 32) * 64 + i]);
        }
        g_WFH[idx * 6 + 5] = __floats2half2_rn(0.f, 0.f);
    }
}

// smem: tb 20 slots x 1024 floats = 80 KB; WPH 80 KB; WFH 48 KB -> 208 KB
static constexpr int TB_FLOATS  = 20 * 1024;
static constexpr int WPH_H2     = 64 * 32 * 10;      // 20480
static constexpr int WFH_H2     = 64 * 32 * 6;       // 12288
static constexpr int SMEM_BYTES = TB_FLOATS * 4 + WPH_H2 * 4 + WFH_H2 * 4;  // 212992

__global__ __launch_bounds__(THREADS, 1)
void gbl_kernel(const float* __restrict__ x, const float* __restrict__ ref,
                float* __restrict__ out) {
    extern __shared__ float smem[];
    float*   tb  = smem;
    __half2* WPH = reinterpret_cast<__half2*>(smem + TB_FLOATS);
    __half2* WFH = WPH + WPH_H2;

    const int tid  = threadIdx.x;
    const int w    = tid >> 5;
    const int lane = tid & 31;
    const int q    = lane & 3;
    const int s0   = w * 2;

    // ---- stage both weight tables once (then no block barriers ever) ----
    {
        uint4*       d = reinterpret_cast<uint4*>(WPH);
        const uint4* s = reinterpret_cast<const uint4*>(g_WPH);
        for (int i = tid; i < WPH_H2 / 4; i += THREADS) d[i] = s[i];
        uint4*       d2 = reinterpret_cast<uint4*>(WFH);
        const uint4* s2 = reinterpret_cast<const uint4*>(g_WFH);
        for (int i = tid; i < WFH_H2 / 4; i += THREADS) d2[i] = s2[i];
    }
    __syncthreads();

    // ---- barrier-free persistent loop: each warp owns its token pair ----
    for (int pair = blockIdx.x * WARPS_PB + w; pair < NPAIRS; pair += GRID * WARPS_PB) {
        const int tok0 = pair * 2;

        // stage 2 tokens, blade-permuted [1..14,0,15], into warp-private slots
        #pragma unroll
        for (int t = 0; t < 2; t++) {
            const float4* xg = reinterpret_cast<const float4*>(x + (size_t)(tok0 + t) * 1024);
            float4* dst = reinterpret_cast<float4*>(tb + (s0 + t) * 1024);
            #pragma unroll
            for (int rep = 0; rep < 8; rep++) {
                float4 v = xg[rep * 32 + lane];          // channel i = rep*8 + lane>>2, quad q
                float firstx = __shfl_sync(0xffffffffu, v.x, lane & ~3);
                float nextx  = __shfl_down_sync(0xffffffffu, v.x, 1);
                float4 o;
                if (q < 3) o = make_float4(v.y, v.z, v.w, nextx);
                else       o = make_float4(v.y, v.z, firstx, v.w);
                dst[rep * 32 + (lane >> 2) * 4 + q] = o;
            }
        }
        __syncwarp();

        // ================= Phase A: fused 4-tensor projection =================
        u64 aPX0[8] = {}, aPY0[8] = {}, aJX0[8] = {}, aJY0[8] = {};
        u64 aPX1[8] = {}, aPY1[8] = {}, aJX1[8] = {}, aJY1[8] = {};
        {
            const uint2* Wu = reinterpret_cast<const uint2*>(WPH) + lane * 5;
            const ulonglong2* xv0 = reinterpret_cast<const ulonglong2*>(tb + s0 * 1024);
            const ulonglong2* xv1 = reinterpret_cast<const ulonglong2*>(tb + (s0 + 1) * 1024);
            #pragma unroll 1
            for (int i = 0; i < 64; i++, Wu += 32 * 5) {
                uint2 ua = Wu[0], ub = Wu[1], uc = Wu[2], ud = Wu[3], ue = Wu[4];
                ulonglong2 a0 = xv0[i * 4 + 0], b0 = xv0[i * 4 + 1],
                           c0 = xv0[i * 4 + 2], d0 = xv0[i * 4 + 3];
                ulonglong2 a1 = xv1[i * 4 + 0], b1 = xv1[i * 4 + 1],
                           c1 = xv1[i * 4 + 2], d1 = xv1[i * 4 + 3];
                {   // prodX = low halves of pair-0 (.x) words
                    MK_PACKS(p0, p1, p2, p3, hlo(ua.x), hlo(ub.x), hlo(uc.x), hlo(ud.x), hlo(ue.x));
                    DO8(aPX0, a0, b0, c0, d0, p0, p1, p2, p3);
                    DO8(aPX1, a1, b1, c1, d1, p0, p1, p2, p3);
                }
                {   // prodY = high halves of pair-0
                    MK_PACKS(p0, p1, p2, p3, hhi(ua.x), hhi(ub.x), hhi(uc.x), hhi(ud.x), hhi(ue.x));
                    DO8(aPY0, a0, b0, c0, d0, p0, p1, p2, p3);
                    DO8(aPY1, a1, b1, c1, d1, p0, p1, p2, p3);
                }
                {   // joinX = low halves of pair-1 (.y) words
                    MK_PACKS(p0, p1, p2, p3, hlo(ua.y), hlo(ub.y), hlo(uc.y), hlo(ud.y), hlo(ue.y));
                    DO8(aJX0, a0, b0, c0, d0, p0, p1, p2, p3);
                    DO8(aJX1, a1, b1, c1, d1, p0, p1, p2, p3);
                }
                {   // joinY = high halves of pair-1
                    MK_PACKS(p0, p1, p2, p3, hhi(ua.y), hhi(ub.y), hhi(uc.y), hhi(ud.y), hhi(ue.y));
                    DO8(aJY0, a0, b0, c0, d0, p0, p1, p2, p3);
                    DO8(aJY1, a1, b1, c1, d1, p0, p1, p2, p3);
                }
            }
        }

        // ================= Phase B: sparse bilinears, feats store =============
        float r0 = __ldg(ref + (size_t)tok0 * 16 + 15);
        float r1 = __ldg(ref + (size_t)(tok0 + 1) * 16 + 15);
        #pragma unroll
        for (int t = 0; t < 2; t++) {
            float px[16], py[16], jx[16], jy[16];
            if (t == 0) { UNPK(aPX0, px); UNPK(aPY0, py); UNPK(aJX0, jx); UNPK(aJY0, jy); }
            else        { UNPK(aPX1, px); UNPK(aPY1, py); UNPK(aJX1, jx); UNPK(aJY1, jy); }
            float r15 = (t == 0) ? r0 : r1;
            #pragma unroll
            for (int k = 0; k < 16; k++) jx[k] *= r15;

            float prod[16] = {}, jn[16] = {};
            gp_mat(prod, px, py, std::make_integer_sequence<int, 16>{});
            jn_mat(jn,   jx, jy, std::make_integer_sequence<int, 16>{});

            // feats overlay x slot, permuted positions + XOR-swizzled float4 slots
            float4* fb = reinterpret_cast<float4*>(tb + (s0 + t) * 1024);
            int ccP = lane, ccJ = lane + 32;
            int swP = ccP & 3, swJ = ccJ & 3;
            fb[ccP * 4 + (0 ^ swP)] = make_float4(prod[1],  prod[2],  prod[3],  prod[4]);
            fb[ccP * 4 + (1 ^ swP)] = make_float4(prod[5],  prod[6],  prod[7],  prod[8]);
            fb[ccP * 4 + (2 ^ swP)] = make_float4(prod[9],  prod[10], prod[11], prod[12]);
            fb[ccP * 4 + (3 ^ swP)] = make_float4(prod[13], prod[14], prod[0],  prod[15]);
            fb[ccJ * 4 + (0 ^ swJ)] = make_float4(jn[1],  jn[2],  jn[3],  jn[4]);
            fb[ccJ * 4 + (1 ^ swJ)] = make_float4(jn[5],  jn[6],  jn[7],  jn[8]);
            fb[ccJ * 4 + (2 ^ swJ)] = make_float4(jn[9],  jn[10], jn[11], jn[12]);
            fb[ccJ * 4 + (3 ^ swJ)] = make_float4(jn[13], jn[14], jn[0],  jn[15]);
        }
        __syncwarp();

        // ================= Phase C: final projection ==========================
        u64 o0a[8] = {}, o0b[8] = {}, o1a[8] = {}, o1b[8] = {};
        {
            const uint2* Vu = reinterpret_cast<const uint2*>(WFH) + lane * 3;
            const ulonglong2* fb0 = reinterpret_cast<const ulonglong2*>(tb + s0 * 1024);
            const ulonglong2* fb1 = reinterpret_cast<const ulonglong2*>(tb + (s0 + 1) * 1024);
            #pragma unroll 1
            for (int cc = 0; cc < 64; cc++, Vu += 32 * 3) {
                uint2 va = Vu[0], vb = Vu[1], vc = Vu[2];   // (g0,g1) (g2,g3) (g4,pad)
                int sw = cc & 3;
                ulonglong2 f00 = fb0[cc * 4 + (0 ^ sw)], f01 = fb0[cc * 4 + (1 ^ sw)],
                           f02 = fb0[cc * 4 + (2 ^ sw)], f03 = fb0[cc * 4 + (3 ^ sw)];
                ulonglong2 f10 = fb1[cc * 4 + (0 ^ sw)], f11 = fb1[cc * 4 + (1 ^ sw)],
                           f12 = fb1[cc * 4 + (2 ^ sw)], f13 = fb1[cc * 4 + (3 ^ sw)];
                {   // output o = lane (low halves)
                    MK_PACKS(p0, p1, p2, p3, hlo(va.x), hlo(va.y), hlo(vb.x), hlo(vb.y), hlo(vc.x));
                    DO8(o0a, f00, f01, f02, f03, p0, p1, p2, p3);
                    DO8(o1a, f10, f11, f12, f13, p0, p1, p2, p3);
                }
                {   // output o+32 (high halves)
                    MK_PACKS(p0, p1, p2, p3, hhi(va.x), hhi(va.y), hhi(vb.x), hhi(vb.y), hhi(vc.x));
                    DO8(o0b, f00, f01, f02, f03, p0, p1, p2, p3);
                    DO8(o1b, f10, f11, f12, f13, p0, p1, p2, p3);
                }
            }
        }

        // ---- stores: natural blade order ----
        {
            float4* op0 = reinterpret_cast<float4*>(out + (size_t)tok0 * 1024);
            float4* op1 = reinterpret_cast<float4*>(out + (size_t)(tok0 + 1) * 1024);
            float v[16];
            UNPK(o0a, v);
            op0[lane * 4 + 0] = make_float4(v[0], v[1], v[2], v[3]);
            op0[lane * 4 + 1] = make_float4(v[4], v[5], v[6], v[7]);
            op0[lane * 4 + 2] = make_float4(v[8], v[9], v[10], v[11]);
            op0[lane * 4 + 3] = make_float4(v[12], v[13], v[14], v[15]);
            UNPK(o0b, v);
            op0[(lane + 32) * 4 + 0] = make_float4(v[0], v[1], v[2], v[3]);
            op0[(lane + 32) * 4 + 1] = make_float4(v[4], v[5], v[6], v[7]);
            op0[(lane + 32) * 4 + 2] = make_float4(v[8], v[9], v[10], v[11]);
            op0[(lane + 32) * 4 + 3] = make_float4(v[12], v[13], v[14], v[15]);
            UNPK(o1a, v);
            op1[lane * 4 + 0] = make_float4(v[0], v[1], v[2], v[3]);
            op1[lane * 4 + 1] = make_float4(v[4], v[5], v[6], v[7]);
            op1[lane * 4 + 2] = make_float4(v[8], v[9], v[10], v[11]);
            op1[lane * 4 + 3] = make_float4(v[12], v[13], v[14], v[15]);
            UNPK(o1b, v);
            op1[(lane + 32) * 4 + 0] = make_float4(v[0], v[1], v[2], v[3]);
            op1[(lane + 32) * 4 + 1] = make_float4(v[4], v[5], v[6], v[7]);
            op1[(lane + 32) * 4 + 2] = make_float4(v[8], v[9], v[10], v[11]);
            op1[(lane + 32) * 4 + 3] = make_float4(v[12], v[13], v[14], v[15]);
        }
        __syncwarp();   // feats reads done before next iteration's x overwrite
    }
}

// ---------------------------------------------------------------------------
extern "C" void kernel_launch(void* const* d_in, const int* in_sizes, int n_in,
                              void* d_out, int out_size) {
    const float* x   = (const float*)d_in[0];
    const float* ref = (const float*)d_in[1];
    const float* wpx = (const float*)d_in[2];
    const float* wpy = (const float*)d_in[3];
    const float* wjx = (const float*)d_in[4];
    const float* wjy = (const float*)d_in[5];
    const float* wf  = (const float*)d_in[6];
    float* out = (float*)d_out;

    prep_kernel<<<8, 256>>>(wpx, wpy, wjx, wjy, wf);

    cudaFuncSetAttribute(gbl_kernel, cudaFuncAttributeMaxDynamicSharedMemorySize, SMEM_BYTES);
    gbl_kernel<<<GRID, THREADS, SMEM_BYTES>>>(x, ref, out);
}

// round 15
// speedup vs baseline: 1.0020x; 1.0020x over previous
#include <cuda_runtime.h>
#include <cuda_fp16.h>
#include <utility>
#include <cstddef>

using u64 = unsigned long long;

// ---------------------------------------------------------------------------
// packed f32x2 primitives (FFMA2 exists only via PTX fma.rn.f32x2)
// ---------------------------------------------------------------------------
__device__ __forceinline__ u64 pack2(float lo, float hi) {
    u64 r; asm("mov.b64 %0, {%1, %2};" : "=l"(r) : "f"(lo), "f"(hi)); return r;
}
__device__ __forceinline__ void unpack2(u64 v, float& lo, float& hi) {
    asm("mov.b64 {%0, %1}, %2;" : "=f"(lo), "=f"(hi) : "l"(v));
}
__device__ __forceinline__ void fma2(u64& d, u64 a, u64 b) {
    asm("fma.rn.f32x2 %0, %1, %2, %3;" : "=l"(d) : "l"(a), "l"(b), "l"(d));
}
__device__ __forceinline__ float hlo(unsigned v) {
    __half2 h = *reinterpret_cast<__half2*>(&v); return __low2float(h);
}
__device__ __forceinline__ float hhi(unsigned v) {
    __half2 h = *reinterpret_cast<__half2*>(&v); return __high2float(h);
}

// 8 packed FMAs covering 16 permuted blade positions.
// Position order: blades [1,2, 3,4, 5,6, 7,8, 9,10, 11,12, 13,14, 0,15]
// pair grades:     g1    g1   g2   g2   g2    g3     g3    (g0,g4)
#define DO8(acc, qa, qb, qc, qd, p0, p1, p2, p3)                         \
    do {                                                                 \
        fma2((acc)[0], (qa).x, (p0)); fma2((acc)[1], (qa).y, (p0));      \
        fma2((acc)[2], (qb).x, (p1)); fma2((acc)[3], (qb).y, (p1));      \
        fma2((acc)[4], (qc).x, (p1)); fma2((acc)[5], (qc).y, (p2));      \
        fma2((acc)[6], (qd).x, (p2)); fma2((acc)[7], (qd).y, (p3));      \
    } while (0)

// unpack 8 pairs (permuted positions) into blade-indexed scalars
#define UNPK(acc, arr)                                                   \
    do {                                                                 \
        unpack2((acc)[0], (arr)[1],  (arr)[2]);                          \
        unpack2((acc)[1], (arr)[3],  (arr)[4]);                          \
        unpack2((acc)[2], (arr)[5],  (arr)[6]);                          \
        unpack2((acc)[3], (arr)[7],  (arr)[8]);                          \
        unpack2((acc)[4], (arr)[9],  (arr)[10]);                         \
        unpack2((acc)[5], (arr)[11], (arr)[12]);                         \
        unpack2((acc)[6], (arr)[13], (arr)[14]);                         \
        unpack2((acc)[7], (arr)[0],  (arr)[15]);                         \
    } while (0)

// build the 4 u64 packs for one tensor from 5 grade weights (f0..f4 = g0..g4)
#define MK_PACKS(p0, p1, p2, p3, f0, f1, f2, f3, f4)                      \
    u64 p0 = pack2(f1, f1), p1 = pack2(f2, f2),                           \
        p2 = pack2(f3, f3), p3 = pack2(f0, f4)

// ---------------------------------------------------------------------------
// Compile-time Clifford algebra G(3,0,1) tables
// Blade order: 1,e0,e1,e2,e3,e01,e02,e03,e12,e13,e23,e012,e013,e023,e123,e0123
// ---------------------------------------------------------------------------
namespace ga {

constexpr int MASK[16]  = {0,1,2,4,8,3,5,9,6,10,12,7,11,13,14,15};

constexpr int mask_to_idx(int m) {
    int r = 0;
    for (int i = 0; i < 16; i++) if (MASK[i] == m) r = i;
    return r;
}
constexpr int swaps(int a, int b) {
    int s = 0;
    for (int q = 0; q < 4; q++)
        if ((b >> q) & 1)
            for (int p = q + 1; p < 4; p++)
                if ((a >> p) & 1) s++;
    return s;
}
constexpr float rsign(int a, int b) { return (swaps(a, b) & 1) ? -1.0f : 1.0f; }

struct Tab { float s[16][16]; int k[16][16]; };

constexpr Tab make_gp() {
    Tab t{};
    for (int i = 0; i < 16; i++)
        for (int j = 0; j < 16; j++) {
            int a = MASK[i], b = MASK[j];
            float sg = rsign(a, b);
            if (a & b & 1) sg = 0.0f;            // e0^2 = 0
            t.s[i][j] = sg;
            t.k[i][j] = mask_to_idx(a ^ b);
        }
    return t;
}
constexpr float dsign(int i) { return rsign(MASK[i], 15 ^ MASK[i]); }
constexpr Tab make_join() {
    Tab t{};
    for (int i = 0; i < 16; i++)
        for (int j = 0; j < 16; j++) {
            int ci = 15 ^ MASK[i], cj = 15 ^ MASK[j];
            if (ci & cj) { t.s[i][j] = 0.0f; t.k[i][j] = 0; }
            else {
                int m = ci | cj;
                int p = mask_to_idx(15 ^ m);
                t.s[i][j] = dsign(i) * dsign(j) * rsign(ci, cj) * dsign(p);
                t.k[i][j] = p;
            }
        }
    return t;
}
constexpr Tab GP = make_gp();
constexpr Tab JN = make_join();

} // namespace ga

// static-for sparse bilinears (all indices compile-time)
template<int I, int J>
__device__ __forceinline__ void gp_term(float* p, const float* a, const float* b) {
    constexpr float s = ga::GP.s[I][J];
    constexpr int   k = ga::GP.k[I][J];
    if constexpr (s != 0.0f) p[k] += s * a[I] * b[J];
}
template<int I, int... Js>
__device__ __forceinline__ void gp_row(float* p, const float* a, const float* b,
                                       std::integer_sequence<int, Js...>) {
    (gp_term<I, Js>(p, a, b), ...);
}
template<int... Is>
__device__ __forceinline__ void gp_mat(float* p, const float* a, const float* b,
                                       std::integer_sequence<int, Is...>) {
    (gp_row<Is>(p, a, b, std::make_integer_sequence<int, 16>{}), ...);
}
template<int I, int J>
__device__ __forceinline__ void jn_term(float* p, const float* a, const float* b) {
    constexpr float s = ga::JN.s[I][J];
    constexpr int   k = ga::JN.k[I][J];
    if constexpr (s != 0.0f) p[k] += s * a[I] * b[J];
}
template<int I, int... Js>
__device__ __forceinline__ void jn_row(float* p, const float* a, const float* b,
                                       std::integer_sequence<int, Js...>) {
    (jn_term<I, Js>(p, a, b), ...);
}
template<int... Is>
__device__ __forceinline__ void jn_mat(float* p, const float* a, const float* b,
                                       std::integer_sequence<int, Is...>) {
    (jn_row<Is>(p, a, b, std::make_integer_sequence<int, 16>{}), ...);
}

// ---------------------------------------------------------------------------
// Problem constants: B=32, N=1024, Cin=64, Cout=64, H=32 -> 32768 tokens
// ---------------------------------------------------------------------------
static constexpr int TOKENS   = 32 * 1024;
static constexpr int NPAIRS   = TOKENS / 2;         // 16384 token pairs
static constexpr int WARPS_PB = 10;                 // 10 warps -> 204 reg budget
static constexpr int THREADS  = WARPS_PB * 32;      // 320
static constexpr int GRID     = 152;                // persistent, 1 CTA/SM

// fp16 weight tables (static __device__ -> no allocation)
// g_WPH: per (i, c) slot: 10 half2  [g0:(PX,PY) (JX,JY), g1:..., g2, g3, g4]
// g_WFH: per (cc, o) slot: 6 half2  [g0:(o,o+32), g1, g2, g3, g4, pad]
__device__ __align__(16) __half2 g_WPH[64 * 32 * 10];
__device__ __align__(16) __half2 g_WFH[64 * 32 * 6];

__global__ void prep_kernel(const float* __restrict__ wpx, const float* __restrict__ wpy,
                            const float* __restrict__ wjx, const float* __restrict__ wjy,
                            const float* __restrict__ wf) {
    int idx = blockIdx.x * blockDim.x + threadIdx.x;     // over 2048 (i,c) slots
    if (idx < 64 * 32) {
        int c = idx & 31;            // lane channel (c for proj, o for final)
        int i = idx >> 5;            // reduction index (i for proj, cc for final)
        #pragma unroll
        for (int g = 0; g < 5; g++) {
            int src = (g * 32 + c) * 64 + i;             // proj weights [5][32][64]
            g_WPH[idx * 10 + g * 2 + 0] = __floats2half2_rn(wpx[src], wpy[src]);
            g_WPH[idx * 10 + g * 2 + 1] = __floats2half2_rn(wjx[src], wjy[src]);
            // final weights [5][64 o][64 cc]; here c = o, i = cc
            g_WFH[idx * 6 + g] = __floats2half2_rn(wf[(g * 64 + c) * 64 + i],
                                                   wf[(g * 64 + c + 32) * 64 + i]);
        }
        g_WFH[idx * 6 + 5] = __floats2half2_rn(0.f, 0.f);
    }
}

// smem: tb 20 slots x 1024 floats = 80 KB; WPH 80 KB; WFH 48 KB -> 208 KB
static constexpr int TB_FLOATS  = 20 * 1024;
static constexpr int WPH_H2     = 64 * 32 * 10;      // 20480
static constexpr int WFH_H2     = 64 * 32 * 6;       // 12288
static constexpr int SMEM_BYTES = TB_FLOATS * 4 + WPH_H2 * 4 + WFH_H2 * 4;  // 212992

__global__ __launch_bounds__(THREADS, 1)
void gbl_kernel(const float* __restrict__ x, const float* __restrict__ ref,
                float* __restrict__ out) {
    extern __shared__ float smem[];
    float*   tb  = smem;
    __half2* WPH = reinterpret_cast<__half2*>(smem + TB_FLOATS);
    __half2* WFH = WPH + WPH_H2;

    const int tid  = threadIdx.x;
    const int w    = tid >> 5;
    const int lane = tid & 31;
    const int q    = lane & 3;
    const int s0   = w * 2;

    // ---- stage both weight tables once (then no block barriers ever) ----
    {
        uint4*       d = reinterpret_cast<uint4*>(WPH);
        const uint4* s = reinterpret_cast<const uint4*>(g_WPH);
        for (int i = tid; i < WPH_H2 / 4; i += THREADS) d[i] = s[i];
        uint4*       d2 = reinterpret_cast<uint4*>(WFH);
        const uint4* s2 = reinterpret_cast<const uint4*>(g_WFH);
        for (int i = tid; i < WFH_H2 / 4; i += THREADS) d2[i] = s2[i];
    }
    __syncthreads();

    // ---- barrier-free persistent loop: each warp owns its token pair ----
    for (int pair = blockIdx.x * WARPS_PB + w; pair < NPAIRS; pair += GRID * WARPS_PB) {
        const int tok0 = pair * 2;

        // stage 2 tokens, blade-permuted [1..14,0,15], into warp-private slots
        #pragma unroll
        for (int t = 0; t < 2; t++) {
            const float4* xg = reinterpret_cast<const float4*>(x + (size_t)(tok0 + t) * 1024);
            float4* dst = reinterpret_cast<float4*>(tb + (s0 + t) * 1024);
            #pragma unroll
            for (int rep = 0; rep < 8; rep++) {
                float4 v = xg[rep * 32 + lane];          // channel i = rep*8 + lane>>2, quad q
                float firstx = __shfl_sync(0xffffffffu, v.x, lane & ~3);
                float nextx  = __shfl_down_sync(0xffffffffu, v.x, 1);
                float4 o;
                if (q < 3) o = make_float4(v.y, v.z, v.w, nextx);
                else       o = make_float4(v.y, v.z, firstx, v.w);
                dst[rep * 32 + (lane >> 2) * 4 + q] = o;
            }
        }
        __syncwarp();

        // ================= Phase A: fused 4-tensor projection =================
        u64 aPX0[8] = {}, aPY0[8] = {}, aJX0[8] = {}, aJY0[8] = {};
        u64 aPX1[8] = {}, aPY1[8] = {}, aJX1[8] = {}, aJY1[8] = {};
        {
            const uint2* Wu = reinterpret_cast<const uint2*>(WPH) + lane * 5;
            const ulonglong2* xv0 = reinterpret_cast<const ulonglong2*>(tb + s0 * 1024);
            const ulonglong2* xv1 = reinterpret_cast<const ulonglong2*>(tb + (s0 + 1) * 1024);
            #pragma unroll 1
            for (int i = 0; i < 64; i++, Wu += 32 * 5) {
                uint2 ua = Wu[0], ub = Wu[1], uc = Wu[2], ud = Wu[3], ue = Wu[4];
                ulonglong2 a0 = xv0[i * 4 + 0], b0 = xv0[i * 4 + 1],
                           c0 = xv0[i * 4 + 2], d0 = xv0[i * 4 + 3];
                ulonglong2 a1 = xv1[i * 4 + 0], b1 = xv1[i * 4 + 1],
                           c1 = xv1[i * 4 + 2], d1 = xv1[i * 4 + 3];
                {   // prodX = low halves of pair-0 (.x) words
                    MK_PACKS(p0, p1, p2, p3, hlo(ua.x), hlo(ub.x), hlo(uc.x), hlo(ud.x), hlo(ue.x));
                    DO8(aPX0, a0, b0, c0, d0, p0, p1, p2, p3);
                    DO8(aPX1, a1, b1, c1, d1, p0, p1, p2, p3);
                }
                {   // prodY = high halves of pair-0
                    MK_PACKS(p0, p1, p2, p3, hhi(ua.x), hhi(ub.x), hhi(uc.x), hhi(ud.x), hhi(ue.x));
                    DO8(aPY0, a0, b0, c0, d0, p0, p1, p2, p3);
                    DO8(aPY1, a1, b1, c1, d1, p0, p1, p2, p3);
                }
                {   // joinX = low halves of pair-1 (.y) words
                    MK_PACKS(p0, p1, p2, p3, hlo(ua.y), hlo(ub.y), hlo(uc.y), hlo(ud.y), hlo(ue.y));
                    DO8(aJX0, a0, b0, c0, d0, p0, p1, p2, p3);
                    DO8(aJX1, a1, b1, c1, d1, p0, p1, p2, p3);
                }
                {   // joinY = high halves of pair-1
                    MK_PACKS(p0, p1, p2, p3, hhi(ua.y), hhi(ub.y), hhi(uc.y), hhi(ud.y), hhi(ue.y));
                    DO8(aJY0, a0, b0, c0, d0, p0, p1, p2, p3);
                    DO8(aJY1, a1, b1, c1, d1, p0, p1, p2, p3);
                }
            }
        }

        // ================= Phase B: sparse bilinears, feats store =============
        float r0 = __ldg(ref + (size_t)tok0 * 16 + 15);
        float r1 = __ldg(ref + (size_t)(tok0 + 1) * 16 + 15);
        #pragma unroll
        for (int t = 0; t < 2; t++) {
            float px[16], py[16], jx[16], jy[16];
            if (t == 0) { UNPK(aPX0, px); UNPK(aPY0, py); UNPK(aJX0, jx); UNPK(aJY0, jy); }
            else        { UNPK(aPX1, px); UNPK(aPY1, py); UNPK(aJX1, jx); UNPK(aJY1, jy); }
            float r15 = (t == 0) ? r0 : r1;
            #pragma unroll
            for (int k = 0; k < 16; k++) jx[k] *= r15;

            float prod[16] = {}, jn[16] = {};
            gp_mat(prod, px, py, std::make_integer_sequence<int, 16>{});
            jn_mat(jn,   jx, jy, std::make_integer_sequence<int, 16>{});

            // feats overlay x slot, permuted positions + XOR-swizzled float4 slots
            float4* fb = reinterpret_cast<float4*>(tb + (s0 + t) * 1024);
            int ccP = lane, ccJ = lane + 32;
            int swP = ccP & 3, swJ = ccJ & 3;
            fb[ccP * 4 + (0 ^ swP)] = make_float4(prod[1],  prod[2],  prod[3],  prod[4]);
            fb[ccP * 4 + (1 ^ swP)] = make_float4(prod[5],  prod[6],  prod[7],  prod[8]);
            fb[ccP * 4 + (2 ^ swP)] = make_float4(prod[9],  prod[10], prod[11], prod[12]);
            fb[ccP * 4 + (3 ^ swP)] = make_float4(prod[13], prod[14], prod[0],  prod[15]);
            fb[ccJ * 4 + (0 ^ swJ)] = make_float4(jn[1],  jn[2],  jn[3],  jn[4]);
            fb[ccJ * 4 + (1 ^ swJ)] = make_float4(jn[5],  jn[6],  jn[7],  jn[8]);
            fb[ccJ * 4 + (2 ^ swJ)] = make_float4(jn[9],  jn[10], jn[11], jn[12]);
            fb[ccJ * 4 + (3 ^ swJ)] = make_float4(jn[13], jn[14], jn[0],  jn[15]);
        }
        __syncwarp();

        // ================= Phase C: final projection ==========================
        u64 o0a[8] = {}, o0b[8] = {}, o1a[8] = {}, o1b[8] = {};
        {
            const uint2* Vu = reinterpret_cast<const uint2*>(WFH) + lane * 3;
            const ulonglong2* fb0 = reinterpret_cast<const ulonglong2*>(tb + s0 * 1024);
            const ulonglong2* fb1 = reinterpret_cast<const ulonglong2*>(tb + (s0 + 1) * 1024);
            #pragma unroll 1
            for (int cc = 0; cc < 64; cc++, Vu += 32 * 3) {
                uint2 va = Vu[0], vb = Vu[1], vc = Vu[2];   // (g0,g1) (g2,g3) (g4,pad)
                int sw = cc & 3;
                ulonglong2 f00 = fb0[cc * 4 + (0 ^ sw)], f01 = fb0[cc * 4 + (1 ^ sw)],
                           f02 = fb0[cc * 4 + (2 ^ sw)], f03 = fb0[cc * 4 + (3 ^ sw)];
                ulonglong2 f10 = fb1[cc * 4 + (0 ^ sw)], f11 = fb1[cc * 4 + (1 ^ sw)],
                           f12 = fb1[cc * 4 + (2 ^ sw)], f13 = fb1[cc * 4 + (3 ^ sw)];
                {   // output o = lane (low halves)
                    MK_PACKS(p0, p1, p2, p3, hlo(va.x), hlo(va.y), hlo(vb.x), hlo(vb.y), hlo(vc.x));
                    DO8(o0a, f00, f01, f02, f03, p0, p1, p2, p3);
                    DO8(o1a, f10, f11, f12, f13, p0, p1, p2, p3);
                }
                {   // output o+32 (high halves)
                    MK_PACKS(p0, p1, p2, p3, hhi(va.x), hhi(va.y), hhi(vb.x), hhi(vb.y), hhi(vc.x));
                    DO8(o0b, f00, f01, f02, f03, p0, p1, p2, p3);
                    DO8(o1b, f10, f11, f12, f13, p0, p1, p2, p3);
                }
            }
        }

        // ---- stores: natural blade order ----
        {
            float4* op0 = reinterpret_cast<float4*>(out + (size_t)tok0 * 1024);
            float4* op1 = reinterpret_cast<float4*>(out + (size_t)(tok0 + 1) * 1024);
            float v[16];
            UNPK(o0a, v);
            op0[lane * 4 + 0] = make_float4(v[0], v[1], v[2], v[3]);
            op0[lane * 4 + 1] = make_float4(v[4], v[5], v[6], v[7]);
            op0[lane * 4 + 2] = make_float4(v[8], v[9], v[10], v[11]);
            op0[lane * 4 + 3] = make_float4(v[12], v[13], v[14], v[15]);
            UNPK(o0b, v);
            op0[(lane + 32) * 4 + 0] = make_float4(v[0], v[1], v[2], v[3]);
            op0[(lane + 32) * 4 + 1] = make_float4(v[4], v[5], v[6], v[7]);
            op0[(lane + 32) * 4 + 2] = make_float4(v[8], v[9], v[10], v[11]);
            op0[(lane + 32) * 4 + 3] = make_float4(v[12], v[13], v[14], v[15]);
            UNPK(o1a, v);
            op1[lane * 4 + 0] = make_float4(v[0], v[1], v[2], v[3]);
            op1[lane * 4 + 1] = make_float4(v[4], v[5], v[6], v[7]);
            op1[lane * 4 + 2] = make_float4(v[8], v[9], v[10], v[11]);
            op1[lane * 4 + 3] = make_float4(v[12], v[13], v[14], v[15]);
            UNPK(o1b, v);
            op1[(lane + 32) * 4 + 0] = make_float4(v[0], v[1], v[2], v[3]);
            op1[(lane + 32) * 4 + 1] = make_float4(v[4], v[5], v[6], v[7]);
            op1[(lane + 32) * 4 + 2] = make_float4(v[8], v[9], v[10], v[11]);
            op1[(lane + 32) * 4 + 3] = make_float4(v[12], v[13], v[14], v[15]);
        }
        __syncwarp();   // feats reads done before next iteration's x overwrite
    }
}

// ---------------------------------------------------------------------------
extern "C" void kernel_launch(void* const* d_in, const int* in_sizes, int n_in,
                              void* d_out, int out_size) {
    const float* x   = (const float*)d_in[0];
    const float* ref = (const float*)d_in[1];
    const float* wpx = (const float*)d_in[2];
    const float* wpy = (const float*)d_in[3];
    const float* wjx = (const float*)d_in[4];
    const float* wjy = (const float*)d_in[5];
    const float* wf  = (const float*)d_in[6];
    float* out = (float*)d_out;

    prep_kernel<<<8, 256>>>(wpx, wpy, wjx, wjy, wf);

    cudaFuncSetAttribute(gbl_kernel, cudaFuncAttributeMaxDynamicSharedMemorySize, SMEM_BYTES);
    gbl_kernel<<<GRID, THREADS, SMEM_BYTES>>>(x, ref, out);
}

// round 17
// speedup vs baseline: 3.1059x; 3.0997x over previous
#include <cuda_runtime.h>
#include <cuda_fp16.h>
#include <utility>
#include <cstddef>

// ---------------------------------------------------------------------------
// Compile-time Clifford algebra G(3,0,1) tables (proven in prior rounds)
// Blade order: 1,e0,e1,e2,e3,e01,e02,e03,e12,e13,e23,e012,e013,e023,e123,e0123
// ---------------------------------------------------------------------------
namespace ga {
constexpr int MASK[16]  = {0,1,2,4,8,3,5,9,6,10,12,7,11,13,14,15};
constexpr int mask_to_idx(int m) {
    int r = 0; for (int i = 0; i < 16; i++) if (MASK[i] == m) r = i; return r;
}
constexpr int swaps(int a, int b) {
    int s = 0;
    for (int q = 0; q < 4; q++) if ((b >> q) & 1)
        for (int p = q + 1; p < 4; p++) if ((a >> p) & 1) s++;
    return s;
}
constexpr float rsign(int a, int b) { return (swaps(a, b) & 1) ? -1.0f : 1.0f; }
struct Tab { float s[16][16]; int k[16][16]; };
constexpr Tab make_gp() {
    Tab t{};
    for (int i = 0; i < 16; i++)
        for (int j = 0; j < 16; j++) {
            int a = MASK[i], b = MASK[j];
            float sg = rsign(a, b);
            if (a & b & 1) sg = 0.0f;
            t.s[i][j] = sg; t.k[i][j] = mask_to_idx(a ^ b);
        }
    return t;
}
constexpr float dsign(int i) { return rsign(MASK[i], 15 ^ MASK[i]); }
constexpr Tab make_join() {
    Tab t{};
    for (int i = 0; i < 16; i++)
        for (int j = 0; j < 16; j++) {
            int ci = 15 ^ MASK[i], cj = 15 ^ MASK[j];
            if (ci & cj) { t.s[i][j] = 0.0f; t.k[i][j] = 0; }
            else {
                int m = ci | cj; int p = mask_to_idx(15 ^ m);
                t.s[i][j] = dsign(i) * dsign(j) * rsign(ci, cj) * dsign(p);
                t.k[i][j] = p;
            }
        }
    return t;
}
constexpr Tab GP = make_gp();
constexpr Tab JN = make_join();
} // namespace ga

template<int I, int J>
__device__ __forceinline__ void gp_term(float* p, const float* a, const float* b) {
    constexpr float s = ga::GP.s[I][J]; constexpr int k = ga::GP.k[I][J];
    if constexpr (s != 0.0f) p[k] += s * a[I] * b[J];
}
template<int I, int... Js>
__device__ __forceinline__ void gp_row(float* p, const float* a, const float* b,
                                       std::integer_sequence<int, Js...>) {
    (gp_term<I, Js>(p, a, b), ...);
}
template<int... Is>
__device__ __forceinline__ void gp_mat(float* p, const float* a, const float* b,
                                       std::integer_sequence<int, Is...>) {
    (gp_row<Is>(p, a, b, std::make_integer_sequence<int, 16>{}), ...);
}
template<int I, int J>
__device__ __forceinline__ void jn_term(float* p, const float* a, const float* b) {
    constexpr float s = ga::JN.s[I][J]; constexpr int k = ga::JN.k[I][J];
    if constexpr (s != 0.0f) p[k] += s * a[I] * b[J];
}
template<int I, int... Js>
__device__ __forceinline__ void jn_row(float* p, const float* a, const float* b,
                                       std::integer_sequence<int, Js...>) {
    (jn_term<I, Js>(p, a, b), ...);
}
template<int... Is>
__device__ __forceinline__ void jn_mat(float* p, const float* a, const float* b,
                                       std::integer_sequence<int, Is...>) {
    (jn_row<Is>(p, a, b, std::make_integer_sequence<int, 16>{}), ...);
}

// ---------------------------------------------------------------------------
// MMA primitives
// ---------------------------------------------------------------------------
__device__ __forceinline__ void mma16816(float* d, const unsigned* a, const unsigned* b) {
    asm volatile("mma.sync.aligned.m16n8k16.row.col.f32.f16.f16.f32 "
        "{%0,%1,%2,%3}, {%4,%5,%6,%7}, {%8,%9}, {%0,%1,%2,%3};"
        : "+f"(d[0]), "+f"(d[1]), "+f"(d[2]), "+f"(d[3])
        : "r"(a[0]), "r"(a[1]), "r"(a[2]), "r"(a[3]), "r"(b[0]), "r"(b[1]));
}
__device__ __forceinline__ void ldsm4(unsigned* a, unsigned addr) {
    asm volatile("ldmatrix.sync.aligned.m8n8.x4.shared.b16 {%0,%1,%2,%3}, [%4];"
        : "=r"(a[0]), "=r"(a[1]), "=r"(a[2]), "=r"(a[3]) : "r"(addr) : "memory");
}
__device__ __forceinline__ unsigned s2u(const void* p) {
    return (unsigned)__cvta_generic_to_shared(p);
}
__device__ __forceinline__ unsigned pack_h2(float a, float b) {
    __half2 h = __halves2half2(__float2half_rn(a), __float2half_rn(b));
    return *reinterpret_cast<unsigned*>(&h);
}

// grade per blade, packed nibbles (k15..k0)
constexpr unsigned long long GRADES = 0x4333322222211110ULL;
constexpr unsigned PAIR_A = 0x0DB97531u;   // phase-C blade pairs (grade-matched)
constexpr unsigned PAIR_B = 0xFECA8642u;

// ---------------------------------------------------------------------------
// Problem constants
// ---------------------------------------------------------------------------
static constexpr int TOKENS  = 32 * 1024;
static constexpr int NTILES  = TOKENS / 16;        // 2048 tiles of 16 tokens
static constexpr int THREADS = 256;
static constexpr int GRID    = 152;

// weight tables in B-fragment order (built by prep)
// WPB: [T 4][nb 4][gr 5][ks 4][lane 32] uint2     (phase A, H=32 outputs)
// WFB: [gr 5][nb 8][ks 4][lane 32] uint2           (phase C, 64 outputs)
__device__ __align__(16) uint2 g_WPB[320 * 32];
__device__ __align__(16) uint2 g_WFB[160 * 32];

__global__ void prep_kernel(const float* __restrict__ wpx, const float* __restrict__ wpy,
                            const float* __restrict__ wjx, const float* __restrict__ wjy,
                            const float* __restrict__ wf) {
    int idx = blockIdx.x * blockDim.x + threadIdx.x;
    if (idx >= 480 * 32) return;
    int lane = idx & 31, grp = idx >> 5;
    int t2 = (lane & 3) * 2, lr = lane >> 2;
    if (grp < 320) {
        int T = grp / 80, rem = grp % 80;
        int nb = rem / 20, rem2 = rem % 20;
        int gr = rem2 >> 2, ks = rem2 & 3;
        const float* ws = (T == 0) ? wpx : (T == 1) ? wpy : (T == 2) ? wjx : wjy;
        const float* row = ws + (size_t)(gr * 32 + nb * 8 + lr) * 64 + ks * 16;
        uint2 v; v.x = pack_h2(row[t2], row[t2 + 1]); v.y = pack_h2(row[t2 + 8], row[t2 + 9]);
        g_WPB[grp * 32 + lane] = v;
    } else {
        int g2 = grp - 320;                       // (gr*8+nb)*4+ks
        int gr = g2 >> 5, rem = g2 & 31;
        int nb = rem >> 2, ks = rem & 3;
        const float* row = wf + (size_t)(gr * 64 + nb * 8 + lr) * 64 + ks * 16;
        uint2 v; v.x = pack_h2(row[t2], row[t2 + 1]); v.y = pack_h2(row[t2 + 8], row[t2 + 9]);
        g_WFB[g2 * 32 + lane] = v;
    }
}

// SMEM layout (bytes). Axs/Fts: [blade 16][tok 16][ch 64] fp16, tok stride 144B,
// blade stride 2336B. OutS (fp32, tok stride 1092 words, o stride 17) overlays Axs+Fts.
static constexpr int AXS_OFF  = 0;
static constexpr int FTS_OFF  = 16 * 2336;                 // 37376
static constexpr int WPB_OFF  = FTS_OFF + 16 * 2336;       // 74752
static constexpr int WFB_OFF  = WPB_OFF + 320 * 256;       // 156672
static constexpr int SMEM_BYTES = WFB_OFF + 160 * 256;     // 197632

__global__ __launch_bounds__(THREADS, 1)
void gbl_kernel(const float* __restrict__ x, const float* __restrict__ ref,
                float* __restrict__ out) {
    extern __shared__ char smem[];
    __half* AxsH = reinterpret_cast<__half*>(smem + AXS_OFF);
    __half* FtsH = reinterpret_cast<__half*>(smem + FTS_OFF);
    char*   WPB  = smem + WPB_OFF;
    char*   WFB  = smem + WFB_OFF;
    float*  OutS = reinterpret_cast<float*>(smem);
    const unsigned sb = s2u(smem);

    const int tid  = threadIdx.x;
    const int w    = tid >> 5;
    const int lane = tid & 31;
    const int g    = lane >> 2;        // group id
    const int t    = lane & 3;         // thread-in-group
    // ldmatrix row mapping
    const int mat  = lane >> 3;
    const int tokr_ld = (lane & 7) + ((mat & 1) << 3);
    const int cbk  = mat >> 1;

    // stage weight tables once
    {
        uint4*       d = reinterpret_cast<uint4*>(WPB);
        const uint4* s = reinterpret_cast<const uint4*>(g_WPB);
        for (int i = tid; i < (320 * 256) / 16; i += THREADS) d[i] = s[i];
        uint4*       d2 = reinterpret_cast<uint4*>(WFB);
        const uint4* s2 = reinterpret_cast<const uint4*>(g_WFB);
        for (int i = tid; i < (160 * 256) / 16; i += THREADS) d2[i] = s2[i];
    }
    __syncthreads();

    const int br = w >> 2;             // 0 = prod branch, 1 = join branch
    const int nb = w & 3;              // phase-A n8 tile
    const int ka  = (PAIR_A >> (w * 4)) & 15;   // phase-C blades
    const int kb  = (PAIR_B >> (w * 4)) & 15;
    const int gra = (int)((GRADES >> (ka * 4)) & 15);
    const int grb = (int)((GRADES >> (kb * 4)) & 15);

    for (int tile = blockIdx.x; tile < NTILES; tile += gridDim.x) {
        const int tok0 = tile * 16;

        // ---- stage x tile: fp32 gmem -> fp16 Axs[k][tok][c] ----
        {
            int tw = ((w & 1) << 3) + g;                    // token 0..15
            const float4* xg = reinterpret_cast<const float4*>(x + (size_t)(tok0 + tw) * 1024);
            #pragma unroll
            for (int it = 0; it < 4; it++) {
                int c = ((w >> 1) << 4) + (it << 2) + t;    // channel 0..63
                float4 v0 = xg[c * 4 + 0], v1 = xg[c * 4 + 1];
                float4 v2 = xg[c * 4 + 2], v3 = xg[c * 4 + 3];
                float vv[16] = {v0.x,v0.y,v0.z,v0.w, v1.x,v1.y,v1.z,v1.w,
                                v2.x,v2.y,v2.z,v2.w, v3.x,v3.y,v3.z,v3.w};
                #pragma unroll
                for (int k = 0; k < 16; k++)
                    AxsH[k * 1168 + tw * 72 + c] = __float2half_rn(vv[k]);
            }
        }
        __syncthreads();   // (1)

        // ================= Phase A: MMA projections =================
        float accX[16][4], accY[16][4];
        #pragma unroll
        for (int k = 0; k < 16; k++)
            #pragma unroll
            for (int j = 0; j < 4; j++) { accX[k][j] = 0.f; accY[k][j] = 0.f; }
        {
            const unsigned abase = sb + AXS_OFF + tokr_ld * 144 + cbk * 16;
            #pragma unroll
            for (int ks = 0; ks < 4; ks++) {
                uint2 bx[5], by[5];
                #pragma unroll
                for (int gr = 0; gr < 5; gr++) {
                    bx[gr] = *reinterpret_cast<const uint2*>(
                        WPB + ((((br * 2 + 0) * 4 + nb) * 5 + gr) * 4 + ks) * 256 + lane * 8);
                    by[gr] = *reinterpret_cast<const uint2*>(
                        WPB + ((((br * 2 + 1) * 4 + nb) * 5 + gr) * 4 + ks) * 256 + lane * 8);
                }
                #pragma unroll
                for (int k = 0; k < 16; k++) {
                    unsigned a[4];
                    ldsm4(a, abase + k * 2336 + ks * 32);
                    constexpr unsigned long long GR = GRADES;
                    const int gr = (int)((GR >> (k * 4)) & 15);
                    mma16816(accX[k], a, reinterpret_cast<const unsigned*>(&bx[gr]));
                    mma16816(accY[k], a, reinterpret_cast<const unsigned*>(&by[gr]));
                }
            }
        }

        // ================= Phase B: bilinear + feats store =================
        {
            float r15lo = 0.f, r15hi = 0.f;
            if (br == 1) {
                r15lo = __ldg(ref + (size_t)(tok0 + g) * 16 + 15);
                r15hi = __ldg(ref + (size_t)(tok0 + g + 8) * 16 + 15);
            }
            const int cc0 = br * 32 + nb * 8 + 2 * t;
            #pragma unroll
            for (int rh = 0; rh < 2; rh++) {
                float lo[16], hi[16];
                const float r15 = rh ? r15hi : r15lo;
                #pragma unroll
                for (int dl = 0; dl < 2; dl++) {
                    float px[16], py[16], res[16];
                    #pragma unroll
                    for (int k = 0; k < 16; k++) {
                        px[k] = accX[k][rh * 2 + dl];
                        py[k] = accY[k][rh * 2 + dl];
                        res[k] = 0.f;
                    }
                    if (br == 0) {
                        gp_mat(res, px, py, std::make_integer_sequence<int, 16>{});
                    } else {
                        #pragma unroll
                        for (int k = 0; k < 16; k++) px[k] *= r15;
                        jn_mat(res, px, py, std::make_integer_sequence<int, 16>{});
                    }
                    float* o = dl ? hi : lo;
                    #pragma unroll
                    for (int k = 0; k < 16; k++) o[k] = res[k];
                }
                const int tokr = g + rh * 8;
                #pragma unroll
                for (int k = 0; k < 16; k++) {
                    __half2 hv = __halves2half2(__float2half_rn(lo[k]),
                                                __float2half_rn(hi[k]));
                    *reinterpret_cast<__half2*>(FtsH + k * 1168 + tokr * 72 + cc0) = hv;
                }
            }
        }
        __syncthreads();   // (2)

        // ================= Phase C: final projection =================
        float oa[8][4], ob[8][4];
        #pragma unroll
        for (int n8 = 0; n8 < 8; n8++)
            #pragma unroll
            for (int j = 0; j < 4; j++) { oa[n8][j] = 0.f; ob[n8][j] = 0.f; }
        {
            const unsigned fbase = sb + FTS_OFF + tokr_ld * 144 + cbk * 16;
            #pragma unroll
            for (int ks = 0; ks < 4; ks++) {
                unsigned aA[4], aB[4];
                ldsm4(aA, fbase + ka * 2336 + ks * 32);
                ldsm4(aB, fbase + kb * 2336 + ks * 32);
                #pragma unroll
                for (int n8 = 0; n8 < 8; n8++) {
                    uint2 Ba = *reinterpret_cast<const uint2*>(
                        WFB + (((gra * 8 + n8) * 4) + ks) * 256 + lane * 8);
                    uint2 Bb = *reinterpret_cast<const uint2*>(
                        WFB + (((grb * 8 + n8) * 4) + ks) * 256 + lane * 8);
                    mma16816(oa[n8], aA, reinterpret_cast<const unsigned*>(&Ba));
                    mma16816(ob[n8], aB, reinterpret_cast<const unsigned*>(&Bb));
                }
            }
        }
        __syncthreads();   // (3) all Axs/Fts reads done; safe to overlay OutS

        // ---- epilogue: OutS transpose stores ----
        #pragma unroll
        for (int n8 = 0; n8 < 8; n8++) {
            const int o0 = n8 * 8 + 2 * t;
            #pragma unroll
            for (int rh = 0; rh < 2; rh++) {
                const int row = (g + rh * 8) * 1092;
                OutS[row + o0 * 17 + ka]       = oa[n8][rh * 2 + 0];
                OutS[row + (o0 + 1) * 17 + ka] = oa[n8][rh * 2 + 1];
                OutS[row + o0 * 17 + kb]       = ob[n8][rh * 2 + 0];
                OutS[row + (o0 + 1) * 17 + kb] = ob[n8][rh * 2 + 1];
            }
        }
        __syncthreads();   // (4)

        // ---- coalesced flush OutS -> gmem ----
        #pragma unroll 1
        for (int f = tid; f < 4096; f += THREADS) {
            int tk = f >> 8, r = f & 255;
            int o = r >> 2, kq = r & 3;
            const float* p = OutS + tk * 1092 + o * 17 + kq * 4;
            float4 v = make_float4(p[0], p[1], p[2], p[3]);
            reinterpret_cast<float4*>(out + (size_t)(tok0 + tk) * 1024)[o * 4 + kq] = v;
        }
        __syncthreads();   // (5) before next tile overwrites Axs/OutS
    }
}

// ---------------------------------------------------------------------------
extern "C" void kernel_launch(void* const* d_in, const int* in_sizes, int n_in,
                              void* d_out, int out_size) {
    const float* x   = (const float*)d_in[0];
    const float* ref = (const float*)d_in[1];
    const float* wpx = (const float*)d_in[2];
    const float* wpy = (const float*)d_in[3];
    const float* wjx = (const float*)d_in[4];
    const float* wjy = (const float*)d_in[5];
    const float* wf  = (const float*)d_in[6];
    float* out = (float*)d_out;

    prep_kernel<<<60, 256>>>(wpx, wpy, wjx, wjy, wf);

    cudaFuncSetAttribute(gbl_kernel, cudaFuncAttributeMaxDynamicSharedMemorySize, SMEM_BYTES);
    gbl_kernel<<<GRID, THREADS, SMEM_BYTES>>>(x, ref, out);
}